// round 1
// baseline (speedup 1.0000x reference)
#include <cuda_runtime.h>
#include <cuda_bf16.h>

// Problem constants (from reference_code)
#define BATCH 32
#define NATOMS 1024
#define ITILE 4          // output rows per block
#define THREADS 256      // 256 threads * 4 j's = 1024 j's per row

// Each block: one frame b, ITILE consecutive i-rows. Loads all NATOMS
// positions of the frame into shared once, then streams out
// ITILE * NATOMS * 3 floats (48 KB) of minimum-image displacements.
__global__ __launch_bounds__(THREADS)
void rij_min_image_kernel(const float* __restrict__ pos,
                          const float* __restrict__ cell,
                          float* __restrict__ out)
{
    __shared__ float spos[NATOMS * 3];   // 12 KB

    const int b  = blockIdx.y;
    const int i0 = blockIdx.x * ITILE;

    // Cooperative load of this frame's positions into shared memory.
    const float* pb = pos + (size_t)b * NATOMS * 3;
    #pragma unroll
    for (int t = 0; t < (NATOMS * 3) / THREADS; ++t) {
        int idx = t * THREADS + threadIdx.x;
        spos[idx] = pb[idx];
    }

    // Box lengths from the diagonal of this frame's cell.
    const float bx = cell[(size_t)b * 9 + 0];
    const float by = cell[(size_t)b * 9 + 4];
    const float bz = cell[(size_t)b * 9 + 8];

    __syncthreads();

    // Each thread owns 4 consecutive j columns.
    const int j0 = threadIdx.x * 4;
    float pjx[4], pjy[4], pjz[4];
    #pragma unroll
    for (int k = 0; k < 4; ++k) {
        pjx[k] = spos[(j0 + k) * 3 + 0];
        pjy[k] = spos[(j0 + k) * 3 + 1];
        pjz[k] = spos[(j0 + k) * 3 + 2];
    }

    float* orow = out + ((size_t)b * NATOMS * NATOMS + (size_t)i0 * NATOMS) * 3;

    #pragma unroll
    for (int ii = 0; ii < ITILE; ++ii) {
        const int i = i0 + ii;
        const float pix = spos[i * 3 + 0];
        const float piy = spos[i * 3 + 1];
        const float piz = spos[i * 3 + 2];

        float v[12];
        #pragma unroll
        for (int k = 0; k < 4; ++k) {
            // Match XLA numerics: IEEE round-to-nearest divide, then rint
            // (ties to even). This keeps the wrap index identical to the
            // reference even at half-integer boundaries.
            float dx = pix - pjx[k];
            dx -= rintf(__fdiv_rn(dx, bx)) * bx;
            float dy = piy - pjy[k];
            dy -= rintf(__fdiv_rn(dy, by)) * by;
            float dz = piz - pjz[k];
            dz -= rintf(__fdiv_rn(dz, bz)) * bz;
            v[k * 3 + 0] = dx;
            v[k * 3 + 1] = dy;
            v[k * 3 + 2] = dz;
        }

        // 12 floats -> 3 x float4 streaming stores, 16B-aligned.
        float4* dst = (float4*)(orow + (size_t)ii * NATOMS * 3 + (size_t)j0 * 3);
        __stcs(dst + 0, make_float4(v[0], v[1],  v[2],  v[3]));
        __stcs(dst + 1, make_float4(v[4], v[5],  v[6],  v[7]));
        __stcs(dst + 2, make_float4(v[8], v[9],  v[10], v[11]));
    }
}

extern "C" void kernel_launch(void* const* d_in, const int* in_sizes, int n_in,
                              void* d_out, int out_size)
{
    const float* positions = (const float*)d_in[0];  // (32, 1024, 3)
    const float* cell      = (const float*)d_in[1];  // (32, 3, 3)
    float* out             = (float*)d_out;          // (32, 1024, 1024, 3)

    dim3 grid(NATOMS / ITILE, BATCH);   // (256, 32) = 8192 blocks
    rij_min_image_kernel<<<grid, THREADS>>>(positions, cell, out);
}